// round 1
// baseline (speedup 1.0000x reference)
#include <cuda_runtime.h>
#include <cstdint>
#include <math.h>

#define HID   2048
#define DRES  1024
#define NRES  4
#define SRES  256
#define BB    4
#define TT    2048
#define MROWS (BB*TT)
#define LEAK  0.1f

// -------- scratch (static device globals; no allocation in kernel_launch) ----
__device__ float g_x[(size_t)MROWS * DRES];       // input projection  [8192,1024]
__device__ float g_states[(size_t)MROWS * DRES];  // reservoir states  [8192,1024]
__device__ float g_out[(size_t)MROWS * HID];      // output projection [8192,2048]
__device__ float g_final[BB * DRES];              // final state       [4,1024]

// ============================================================================
// tf32 mma.sync GEMM:  C[M,N] = A[M,K] @ B[K,N] + bias[N]   (all fp32 memory)
// 128x128 CTA tile, BK=16, 256 threads, warp tile 32x64 (m16n8k8)
// ============================================================================
__device__ __forceinline__ uint32_t f2tf32(float f) {
    uint32_t r; asm("cvt.rna.tf32.f32 %0, %1;" : "=r"(r) : "f"(f)); return r;
}

__global__ __launch_bounds__(256) void gemm_tf32_kernel(
    const float* __restrict__ A, const float* __restrict__ Bm,
    const float* __restrict__ bias, float* __restrict__ C,
    int M, int N, int K)
{
    __shared__ float As[128][20];   // [m][k], pad 4 -> conflict-free frag loads
    __shared__ float Bs[16][136];   // [k][n], pad 8 -> conflict-free frag loads

    int tid = threadIdx.x;
    int wid = tid >> 5, lane = tid & 31;
    int g = lane >> 2, tig = lane & 3;
    int m0 = blockIdx.y * 128, n0 = blockIdx.x * 128;
    int wm = (wid >> 1) * 32;     // warp row base
    int wn = (wid & 1) * 64;      // warp col base

    float acc[2][8][4];
    #pragma unroll
    for (int i = 0; i < 2; i++)
        #pragma unroll
        for (int j = 0; j < 8; j++)
            #pragma unroll
            for (int k = 0; k < 4; k++) acc[i][j][k] = 0.f;

    for (int k0 = 0; k0 < K; k0 += 16) {
        // load A tile (128x16): 512 float4, 2 per thread
        #pragma unroll
        for (int i = 0; i < 2; i++) {
            int v = tid + i * 256;
            int row = v >> 2, kv = (v & 3) << 2;
            float4 t = *(const float4*)(A + (size_t)(m0 + row) * K + k0 + kv);
            As[row][kv + 0] = t.x; As[row][kv + 1] = t.y;
            As[row][kv + 2] = t.z; As[row][kv + 3] = t.w;
        }
        // load B tile (16x128): 512 float4, 2 per thread
        #pragma unroll
        for (int i = 0; i < 2; i++) {
            int v = tid + i * 256;
            int kr = v >> 5, nv = (v & 31) << 2;
            float4 t = *(const float4*)(Bm + (size_t)(k0 + kr) * N + n0 + nv);
            Bs[kr][nv + 0] = t.x; Bs[kr][nv + 1] = t.y;
            Bs[kr][nv + 2] = t.z; Bs[kr][nv + 3] = t.w;
        }
        __syncthreads();

        #pragma unroll
        for (int ks = 0; ks < 16; ks += 8) {
            uint32_t af[2][4];
            #pragma unroll
            for (int tm = 0; tm < 2; tm++) {
                int rb = wm + tm * 16 + g;
                af[tm][0] = f2tf32(As[rb    ][ks     + tig]);
                af[tm][1] = f2tf32(As[rb + 8][ks     + tig]);
                af[tm][2] = f2tf32(As[rb    ][ks + 4 + tig]);
                af[tm][3] = f2tf32(As[rb + 8][ks + 4 + tig]);
            }
            uint32_t bf[8][2];
            #pragma unroll
            for (int tn = 0; tn < 8; tn++) {
                int col = wn + tn * 8 + g;
                bf[tn][0] = f2tf32(Bs[ks     + tig][col]);
                bf[tn][1] = f2tf32(Bs[ks + 4 + tig][col]);
            }
            #pragma unroll
            for (int tm = 0; tm < 2; tm++)
                #pragma unroll
                for (int tn = 0; tn < 8; tn++) {
                    asm volatile(
                        "mma.sync.aligned.m16n8k8.row.col.f32.tf32.tf32.f32 "
                        "{%0,%1,%2,%3}, {%4,%5,%6,%7}, {%8,%9}, {%0,%1,%2,%3};"
                        : "+f"(acc[tm][tn][0]), "+f"(acc[tm][tn][1]),
                          "+f"(acc[tm][tn][2]), "+f"(acc[tm][tn][3])
                        : "r"(af[tm][0]), "r"(af[tm][1]), "r"(af[tm][2]), "r"(af[tm][3]),
                          "r"(bf[tn][0]), "r"(bf[tn][1]));
                }
        }
        __syncthreads();
    }

    // epilogue: add bias, store (float2 pairs are contiguous in N)
    #pragma unroll
    for (int tm = 0; tm < 2; tm++) {
        int row0 = m0 + wm + tm * 16 + g;
        #pragma unroll
        for (int tn = 0; tn < 8; tn++) {
            int col = n0 + wn + tn * 8 + tig * 2;
            float b0 = bias[col], b1 = bias[col + 1];
            float2 v0 = make_float2(acc[tm][tn][0] + b0, acc[tm][tn][1] + b1);
            float2 v1 = make_float2(acc[tm][tn][2] + b0, acc[tm][tn][3] + b1);
            *(float2*)(C + (size_t)row0 * N + col) = v0;
            *(float2*)(C + (size_t)(row0 + 8) * N + col) = v1;
        }
    }
}

// ============================================================================
// Reservoir scan: 16 chains (b,r), 4-CTA cluster per chain, W in registers.
// Each CTA owns 64 output rows; state exchanged via DSMEM + mbarriers.
// ============================================================================
__device__ __forceinline__ uint32_t su32(const void* p) {
    return (uint32_t)__cvta_generic_to_shared(p);
}

__device__ __forceinline__ void mbar_init(uint32_t a, uint32_t cnt) {
    asm volatile("mbarrier.init.shared.b64 [%0], %1;" :: "r"(a), "r"(cnt) : "memory");
}
__device__ __forceinline__ void mbar_arrive_local(uint32_t a) {
    asm volatile("mbarrier.arrive.shared.b64 _, [%0];" :: "r"(a) : "memory");
}
__device__ __forceinline__ void mbar_arrive_cluster(uint32_t local_addr, uint32_t rank) {
    asm volatile(
        "{\n\t.reg .b32 ra;\n\t"
        "mapa.shared::cluster.u32 ra, %0, %1;\n\t"
        "mbarrier.arrive.release.cluster.shared::cluster.b64 _, [ra];\n\t}"
        :: "r"(local_addr), "r"(rank) : "memory");
}
__device__ __forceinline__ void st_cluster_f32(uint32_t local_addr, uint32_t rank, float v) {
    asm volatile(
        "{\n\t.reg .b32 ra;\n\t"
        "mapa.shared::cluster.u32 ra, %0, %1;\n\t"
        "st.shared::cluster.f32 [ra], %2;\n\t}"
        :: "r"(local_addr), "r"(rank), "f"(v) : "memory");
}
__device__ __forceinline__ void mbar_wait_parity(uint32_t a, uint32_t parity) {
    uint32_t done;
    asm volatile(
        "{\n\t.reg .pred p;\n\t"
        "mbarrier.try_wait.parity.acquire.cluster.shared::cta.b64 p, [%1], %2, 0x989680;\n\t"
        "selp.b32 %0, 1, 0, p;\n\t}"
        : "=r"(done) : "r"(a), "r"(parity) : "memory");
    while (!done) {
        asm volatile(
            "{\n\t.reg .pred p;\n\t"
            "mbarrier.try_wait.parity.acquire.cluster.shared::cta.b64 p, [%1], %2, 0x989680;\n\t"
            "selp.b32 %0, 1, 0, p;\n\t}"
            : "=r"(done) : "r"(a), "r"(parity) : "memory");
    }
}

__global__ __launch_bounds__(256) __cluster_dims__(4, 1, 1)
void scan_kernel(const float* __restrict__ xin, const float* __restrict__ prev,
                 const float* __restrict__ wres, float* __restrict__ states,
                 float* __restrict__ finalst)
{
    // state buffers: 4 quarters of 64 floats, each padded to 68 (bank shift + 16B align)
    __shared__ float sbuf[2][4 * 68];
    __shared__ __align__(8) uint64_t mbar[2];

    int tid = threadIdx.x;
    uint32_t rank;
    asm("mov.u32 %0, %%cluster_ctarank;" : "=r"(rank));
    int chain = blockIdx.x >> 2;        // 0..15
    int b = chain >> 2, r = chain & 3;
    int klocal = tid >> 2;              // 0..63 : output row within this CTA
    int q = tid & 3;                    // j-quarter
    int kg = rank * 64 + klocal;        // global output row 0..255

    uint32_t sbuf_a[2] = { su32(&sbuf[0][0]), su32(&sbuf[1][0]) };
    uint32_t mbar_a[2] = { su32(&mbar[0]),    su32(&mbar[1])    };

    // ---- load my W chunk into registers: W[r][kg][q*64 .. q*64+63] ----
    float w[64];
    {
        const float* wp = wres + ((size_t)(r * 256 + kg) * 256 + q * 64);
        #pragma unroll
        for (int i = 0; i < 16; i++) {
            float4 v = *(const float4*)(wp + 4 * i);
            w[4*i] = v.x; w[4*i+1] = v.y; w[4*i+2] = v.z; w[4*i+3] = v.w;
        }
    }
    // ---- init state buffer 0 from prev_state (each CTA loads all 256) ----
    {
        int j = tid;
        sbuf[0][(j >> 6) * 68 + (j & 63)] = prev[b * 1024 + r * 256 + j];
    }
    if (tid == 0) {
        mbar_init(mbar_a[0], 4);
        mbar_init(mbar_a[1], 4);
    }
    __syncthreads();
    if (tid == 0) {   // pre-arm buffer 0 so step 0's wait passes
        mbar_arrive_local(mbar_a[0]); mbar_arrive_local(mbar_a[0]);
        mbar_arrive_local(mbar_a[0]); mbar_arrive_local(mbar_a[0]);
    }
    // all mbarriers must be visible cluster-wide before any remote arrive
    asm volatile("barrier.cluster.arrive.aligned;" ::: "memory");
    asm volatile("barrier.cluster.wait.aligned;"   ::: "memory");

    int mypos = (kg >> 6) * 68 + (kg & 63);
    const float* xbase = xin + (size_t)b * TT * 1024 + r * 256 + kg;
    float* stbase = states + (size_t)b * TT * 1024 + r * 256 + kg;

    for (int t = 0; t < TT; t++) {
        int cur = t & 1, nxt = cur ^ 1;
        float xv = 0.f;
        if (q == 0) xv = xbase[(size_t)t * 1024];   // overlap LDG with wait

        mbar_wait_parity(mbar_a[cur], (t >> 1) & 1);

        // partial dot: my quarter of row kg
        float acc = 0.f;
        const float* sp = &sbuf[cur][q * 68];
        #pragma unroll
        for (int i = 0; i < 16; i++) {
            float4 sv = *(const float4*)(sp + 4 * i);
            acc = fmaf(w[4*i  ], sv.x, acc);
            acc = fmaf(w[4*i+1], sv.y, acc);
            acc = fmaf(w[4*i+2], sv.z, acc);
            acc = fmaf(w[4*i+3], sv.w, acc);
        }
        acc += __shfl_xor_sync(0xffffffffu, acc, 1);
        acc += __shfl_xor_sync(0xffffffffu, acc, 2);

        if (q == 0) {
            float sold = sbuf[cur][mypos];
            float snew = (1.0f - LEAK) * sold + LEAK * tanhf(acc + xv);
            stbase[(size_t)t * 1024] = snew;
            if (t == TT - 1) finalst[b * 1024 + r * 256 + kg] = snew;
            uint32_t loc = sbuf_a[nxt] + (uint32_t)mypos * 4u;
            #pragma unroll
            for (uint32_t p = 0; p < 4; p++) st_cluster_f32(loc, p, snew);
        }
        __syncthreads();   // all reads of sbuf[cur] + all pushes done
        if (tid < 4) mbar_arrive_cluster(mbar_a[nxt], (uint32_t)tid);
    }

    // keep cluster alive until all in-flight DSMEM traffic lands
    asm volatile("barrier.cluster.arrive.aligned;" ::: "memory");
    asm volatile("barrier.cluster.wait.aligned;"   ::: "memory");
}

// ============================================================================
// RMSNorm epilogue: y = (hs + out) * rsqrt(mean((hs+out)^2) + eps) * ln_w
// ============================================================================
__global__ __launch_bounds__(256) void rmsnorm_kernel(
    const float* __restrict__ hs, const float* __restrict__ ot,
    const float* __restrict__ lnw, float* __restrict__ y)
{
    __shared__ float red[8];
    int row = blockIdx.x, tid = threadIdx.x;
    const float4* h4 = (const float4*)(hs + (size_t)row * HID);
    const float4* o4 = (const float4*)(ot + (size_t)row * HID);
    const float4* l4 = (const float4*)lnw;
    float4* y4 = (float4*)(y + (size_t)row * HID);

    float4 v[2];
    float ss = 0.f;
    #pragma unroll
    for (int i = 0; i < 2; i++) {
        int idx = tid + i * 256;
        float4 a = h4[idx], b = o4[idx];
        float4 s = make_float4(a.x + b.x, a.y + b.y, a.z + b.z, a.w + b.w);
        v[i] = s;
        ss += s.x * s.x + s.y * s.y + s.z * s.z + s.w * s.w;
    }
    #pragma unroll
    for (int off = 16; off; off >>= 1) ss += __shfl_xor_sync(0xffffffffu, ss, off);
    if ((tid & 31) == 0) red[tid >> 5] = ss;
    __syncthreads();
    float tot = 0.f;
    #pragma unroll
    for (int i = 0; i < 8; i++) tot += red[i];
    float scale = rsqrtf(tot * (1.0f / HID) + 1e-6f);
    #pragma unroll
    for (int i = 0; i < 2; i++) {
        int idx = tid + i * 256;
        float4 lw = l4[idx];
        float4 s = v[i];
        y4[idx] = make_float4(s.x * scale * lw.x, s.y * scale * lw.y,
                              s.z * scale * lw.z, s.w * scale * lw.w);
    }
}

__global__ void copy_final_kernel(float* __restrict__ dst) {
    int i = blockIdx.x * 256 + threadIdx.x;
    if (i < BB * DRES) dst[i] = g_final[i];
}

// ============================================================================
extern "C" void kernel_launch(void* const* d_in, const int* in_sizes, int n_in,
                              void* d_out, int out_size)
{
    const float* hs   = (const float*)d_in[0];
    const float* prev = (const float*)d_in[1];
    const float* w_in = (const float*)d_in[2];
    const float* b_in = (const float*)d_in[3];
    const float* wres = (const float*)d_in[4];
    const float* wout = (const float*)d_in[5];
    const float* bout = (const float*)d_in[6];
    const float* lnw  = (const float*)d_in[7];
    float* out = (float*)d_out;

    void *px, *ps, *po, *pf;
    cudaGetSymbolAddress(&px, g_x);
    cudaGetSymbolAddress(&ps, g_states);
    cudaGetSymbolAddress(&po, g_out);
    cudaGetSymbolAddress(&pf, g_final);
    float* gx = (float*)px;
    float* gs = (float*)ps;
    float* go = (float*)po;
    float* gf = (float*)pf;

    // 1) x = hs @ w_in + b_in        [8192,1024]
    gemm_tf32_kernel<<<dim3(DRES / 128, MROWS / 128), 256>>>(
        hs, w_in, b_in, gx, MROWS, DRES, HID);

    // 2) reservoir scan -> states, final
    scan_kernel<<<64, 256>>>(gx, prev, wres, gs, gf);

    // 3) out = states @ w_out + b_out  [8192,2048]
    gemm_tf32_kernel<<<dim3(HID / 128, MROWS / 128), 256>>>(
        gs, wout, bout, go, MROWS, HID, DRES);

    // 4) y = RMSNorm(hs + out) * ln_w
    rmsnorm_kernel<<<MROWS, 256>>>(hs, go, lnw, out);

    // 5) final state appended after y (if the output buffer carries it)
    if (out_size >= MROWS * HID + BB * DRES) {
        float* fdst = out + (out_size - BB * DRES);
        copy_final_kernel<<<(BB * DRES + 255) / 256, 256>>>(fdst);
    }
}